// round 14
// baseline (speedup 1.0000x reference)
#include <cuda_runtime.h>

#define B 512
#define T 512
#define H 128
#define G4 (4 * H)  // 512

typedef unsigned long long u64;

// g_P stores P = 2^{min(2*log2e*w1e, 15)} as [b][h/4][t'][perm(h%4)] quads,
// perm = {0,2,1,3} (pair-interleaved for f32x2 lanes)
__device__ float g_P[(size_t)B * H * T];

#define K2LOG2E 2.885390082f  // 2*log2(e)
#define ONE2 0x3F8000003F800000ULL

__device__ __forceinline__ float ex2f(float x) {
    float r;
    asm("ex2.approx.f32 %0, %1;" : "=f"(r) : "f"(x));
    return r;
}
__device__ __forceinline__ float rcpf(float x) {
    float r;
    asm("rcp.approx.f32 %0, %1;" : "=f"(r) : "f"(x));
    return r;
}
__device__ __forceinline__ float copysign_bits(float mag, float sgn) {
    unsigned int m = __float_as_uint(mag) & 0x7fffffffu;
    unsigned int s = __float_as_uint(sgn) & 0x80000000u;
    return __uint_as_float(m | s);
}
// ---- packed f32x2 (sm_100a) ----
__device__ __forceinline__ u64 fma2(u64 a, u64 b, u64 c) {
    u64 d;
    asm("fma.rn.f32x2 %0, %1, %2, %3;" : "=l"(d) : "l"(a), "l"(b), "l"(c));
    return d;
}
__device__ __forceinline__ u64 mul2(u64 a, u64 b) {
    u64 d;
    asm("mul.rn.f32x2 %0, %1, %2;" : "=l"(d) : "l"(a), "l"(b));
    return d;
}
__device__ __forceinline__ void unpack2(u64 v, float& lo, float& hi) {
    asm("mov.b64 {%0, %1}, %2;" : "=f"(lo), "=f"(hi) : "l"(v));
}
__device__ __forceinline__ u64 pack_dup(float v) {
    u64 r;
    asm("mov.b64 %0, {%1, %1};" : "=l"(r) : "f"(v));
    return r;
}

// ---- gate tanh: negative-exponent safe form + Newton (accurate, NaN-proof) ----
__device__ __forceinline__ float tanh_safe(float x) {
    float y = x * K2LOG2E;
    float m = fminf(y, -y);
    float E = ex2f(m);
    float den = E + 1.0f;
    float r = rcpf(den);
    r = r * fmaf(-den, r, 2.0f);
    float t = (1.0f - E) * r;
    return copysign_bits(t, x);
}

// ---------------- P = 2^{clamp(...)}: transposed, pair-interleaved quads ----------------
__global__ void __launch_bounds__(256) w1e_kernel(const float* __restrict__ enc,
                                                  const float* __restrict__ W1) {
    extern __shared__ float smem[];
    float* sW1 = smem;
    float* senc = smem + 128 * 128;
    int tid = threadIdx.x;
    int b = blockIdx.x >> 3;
    int t0 = (blockIdx.x & 7) * 64;

    for (int i = tid; i < 128 * 128; i += 256) sW1[i] = W1[i];
    for (int i = tid; i < 64 * 128; i += 256) {
        int r = i >> 7, k = i & 127;
        senc[r * 129 + k] = enc[((size_t)b * T + t0 + r) * H + k];
    }
    __syncthreads();

    int t = tid & 63, hg = tid >> 6;
    float acc[32];
#pragma unroll
    for (int i = 0; i < 32; i++) acc[i] = 0.0f;
#pragma unroll 4
    for (int k = 0; k < 128; k++) {
        float e = senc[t * 129 + k];
        const float4* w4 = (const float4*)(sW1 + k * 128 + hg * 32);
#pragma unroll
        for (int q = 0; q < 8; q++) {
            float4 w = w4[q];
            acc[q * 4 + 0] = fmaf(e, w.x, acc[q * 4 + 0]);
            acc[q * 4 + 1] = fmaf(e, w.y, acc[q * 4 + 1]);
            acc[q * 4 + 2] = fmaf(e, w.z, acc[q * 4 + 2]);
            acc[q * 4 + 3] = fmaf(e, w.w, acc[q * 4 + 3]);
        }
    }
    float4* gp = (float4*)g_P;
#pragma unroll
    for (int i4 = 0; i4 < 8; i4++) {
        // pair-interleaved: slots hold h-offsets {0,2,1,3}
        float4 o = make_float4(ex2f(fminf(acc[i4 * 4 + 0] * K2LOG2E, 15.0f)),
                               ex2f(fminf(acc[i4 * 4 + 2] * K2LOG2E, 15.0f)),
                               ex2f(fminf(acc[i4 * 4 + 1] * K2LOG2E, 15.0f)),
                               ex2f(fminf(acc[i4 * 4 + 3] * K2LOG2E, 15.0f)));
        gp[((size_t)b * 32 + hg * 8 + i4) * T + t0 + t] = o;
    }
}

// perm slot for h-index j within its quad: {0,2,1,3}
__device__ __forceinline__ int perm_slot(int j) {
    return (j & ~3) | ((j & 1) << 1) | ((j >> 1) & 1);
}

// ---------------- persistent per-batch decoder: 512 threads, 1 t' per thread ----------------
__global__ void __launch_bounds__(512, 2) decoder_kernel(
    const float* __restrict__ x, const float* __restrict__ h0,
    const float* __restrict__ c0, const float* __restrict__ kern,
    const float* __restrict__ reck, const float* __restrict__ bias,
    const float* __restrict__ W2, const float* __restrict__ V,
    float* __restrict__ out) {
    __shared__ float sh[H];
    __shared__ float4 sEu4[32];     // Eu quads (pair-interleaved)
    __shared__ float4 sv4[32];      // -2V quads (pair-interleaved)
    __shared__ float sVs[H];
    __shared__ float4 spart4[512];  // phase A/C partials
    __shared__ float sact[G4];      // gate activations
    __shared__ float sK0[G4], sK1[G4], sb[G4];
    __shared__ float sx[T * 2];
    __shared__ float sptr[2];
    __shared__ float s_sumV;
    __shared__ float rv[16];
    __shared__ int ri[16];

    int tid = threadIdx.x;
    int b = blockIdx.x;
    int lane = tid & 31, wid = tid >> 5;

    for (int i = tid; i < T * 2; i += 512) sx[i] = x[(size_t)b * T * 2 + i];
    sK0[tid] = kern[tid];
    sK1[tid] = kern[G4 + tid];
    sb[tid] = bias[tid];
    if (tid < H) { sh[tid] = h0[b * H + tid]; sVs[tid] = V[tid]; }
    float creg = (tid < H) ? c0[b * H + tid] : 0.0f;
    if (tid == 0) { sptr[0] = 1.0f; sptr[1] = 1.0f; }
    __syncthreads();
    if (tid < H) ((float*)sv4)[perm_slot(tid)] = -2.0f * sVs[tid];
    if (tid == 0) {
        float sv = 0.0f;
        for (int h = 0; h < H; h++) sv += sVs[h];
        s_sumV = sv;
    }
    __syncthreads();
    float sumV = s_sumV;

    const ulonglong2* wp8 = (const ulonglong2*)((const float4*)g_P + (size_t)b * 32 * T + tid);
    bool is_g = ((tid >> 7) == 2);  // warp-uniform g-gate quarter

    for (int s = 0; s < T; s++) {
        // ---- A: partial z, thread (p = h-quarter, q = gate quad), f32x2 ----
        {
            int p = tid >> 7, q = tid & 127;
            const ulonglong2* rk = (const ulonglong2*)((const float4*)reck + q)
                                   + (size_t)(p * 32) * 128;
            u64 a01 = 0, a23 = 0;
            const float* shb = sh + p * 32;
#pragma unroll
            for (int h = 0; h < 32; h++) {
                u64 hh = pack_dup(shb[h]);
                ulonglong2 w = __ldg(rk + (size_t)h * 128);
                a01 = fma2(hh, w.x, a01);
                a23 = fma2(hh, w.y, a23);
            }
            *(ulonglong2*)&spart4[tid] = make_ulonglong2(a01, a23);
        }
        __syncthreads();

        // ---- B1: z-reduce + activation, one gate per thread ----
        {
            const float* sp = (const float*)spart4;
            float p0 = sptr[0], p1 = sptr[1];
            float z = fmaf(p1, sK1[tid], fmaf(p0, sK0[tid], sb[tid]))
                    + ((sp[tid] + sp[512 + tid]) + (sp[1024 + tid] + sp[1536 + tid]));
            float t = tanh_safe(is_g ? z : 0.5f * z);
            sact[tid] = is_g ? t : fmaf(0.5f, t, 0.5f);
        }
        __syncthreads();

        // ---- B2: cell update (threads 0..127) ----
        if (tid < H) {
            float c2 = sact[tid + H] * creg + sact[tid] * sact[tid + 2 * H];
            creg = c2;
            sh[tid] = sact[tid + 3 * H] * tanh_safe(c2);
        }
        __syncthreads();

        // ---- C: partial u, thread (p2 = h-16th, g = out quad), f32x2 ----
        {
            int p2 = tid >> 5, g = tid & 31;
            const ulonglong2* w2 = (const ulonglong2*)((const float4*)W2 + g)
                                   + (size_t)(p2 * 8) * 32;
            u64 a01 = 0, a23 = 0;
            const float* shb = sh + p2 * 8;
#pragma unroll
            for (int h = 0; h < 8; h++) {
                u64 hh = pack_dup(shb[h]);
                ulonglong2 w = __ldg(w2 + (size_t)h * 32);
                a01 = fma2(hh, w.x, a01);
                a23 = fma2(hh, w.y, a23);
            }
            *(ulonglong2*)&spart4[tid] = make_ulonglong2(a01, a23);
        }
        __syncthreads();

        // ---- C-reduce: Eu[j] = 2^{clamp(u*2log2e)} -> pair-interleaved slot ----
        if (tid < H) {
            const float* sp = (const float*)spart4;
            float u = 0.0f;
#pragma unroll
            for (int p2 = 0; p2 < 16; p2++) u += sp[p2 * 128 + tid];
            ((float*)sEu4)[perm_slot(tid)] = ex2f(fminf(u * K2LOG2E, 15.0f));
        }
        __syncthreads();

        // ---- D: score(t'=tid), f32x2 4-way combined rcp, pair-interleaved ----
        float acc0 = 0.0f, acc1 = 0.0f;
#pragma unroll
        for (int qd = 0; qd < 32; qd++) {
            ulonglong2 Pq = __ldcg(wp8 + (size_t)qd * T);          // {P02, P13}
            ulonglong2 Eq = *(const ulonglong2*)&sEu4[qd];          // {Eu02, Eu13}
            ulonglong2 Vq = *(const ulonglong2*)&sv4[qd];           // {V02, V13}
            u64 dA = fma2(Pq.x, Eq.x, ONE2);   // {d0, d2}
            u64 dB = fma2(Pq.y, Eq.y, ONE2);   // {d1, d3}
            u64 prod = mul2(dA, dB);           // {d0*d1, d2*d3}
            u64 nA = mul2(Vq.x, dB);           // {V0*d1, V2*d3}
            u64 n2 = fma2(Vq.y, dA, nA);       // {n01, n23}
            float px, py, n01, n23;
            unpack2(prod, px, py);
            unpack2(n2, n01, n23);
            float num = fmaf(n23, px, n01 * py);
            float r = rcpf(px * py);
            if (qd & 1) acc1 = fmaf(num, r, acc1);
            else        acc0 = fmaf(num, r, acc0);
        }
        float score = sumV + (acc0 + acc1);
        __stcs(out + ((size_t)b * T + s) * T + tid, score);

        // ---- argmax (tie -> lowest index) + pointer select ----
        float best = score;
        int bidx = tid;
#pragma unroll
        for (int o = 16; o > 0; o >>= 1) {
            float ov = __shfl_xor_sync(0xffffffffu, best, o);
            int oi = __shfl_xor_sync(0xffffffffu, bidx, o);
            if (ov > best || (ov == best && oi < bidx)) { best = ov; bidx = oi; }
        }
        if (lane == 0) { rv[wid] = best; ri[wid] = bidx; }
        __syncthreads();
        if (wid == 0) {
            float bb = (lane < 16) ? rv[lane] : rv[0];
            int bi = (lane < 16) ? ri[lane] : ri[0];
#pragma unroll
            for (int o = 8; o > 0; o >>= 1) {
                float ov = __shfl_xor_sync(0xffffffffu, bb, o);
                int oi = __shfl_xor_sync(0xffffffffu, bi, o);
                if (ov > bb || (ov == bb && oi < bi)) { bb = ov; bi = oi; }
            }
            if (lane == 0) {
                sptr[0] = sx[bi * 2];
                sptr[1] = sx[bi * 2 + 1];
            }
        }
        __syncthreads();
    }
}

// ---------------- launch: 2 graph nodes ----------------
extern "C" void kernel_launch(void* const* d_in, const int* in_sizes, int n_in,
                              void* d_out, int out_size) {
    const float* x = (const float*)d_in[0];
    const float* enc = (const float*)d_in[1];
    const float* h0 = (const float*)d_in[2];
    const float* c0 = (const float*)d_in[3];
    const float* kern = (const float*)d_in[4];
    const float* reck = (const float*)d_in[5];
    const float* bias = (const float*)d_in[6];
    const float* W1 = (const float*)d_in[7];
    const float* W2 = (const float*)d_in[8];
    const float* V = (const float*)d_in[9];
    float* out = (float*)d_out;

    const int smem_w1e = (128 * 128 + 64 * 129) * 4;  // 98560 B
    cudaFuncSetAttribute(w1e_kernel, cudaFuncAttributeMaxDynamicSharedMemorySize, smem_w1e);
    w1e_kernel<<<B * 8, 256, smem_w1e>>>(enc, W1);
    decoder_kernel<<<B, 512>>>(x, h0, c0, kern, reck, bias, W2, V, out);
}

// round 15
// speedup vs baseline: 1.8214x; 1.8214x over previous
#include <cuda_runtime.h>

#define B 512
#define T 512
#define H 128
#define G4 (4 * H)  // 512

// g_P stores P = 2^{min(2*log2e*w1e, 15)}  as [b][h/4][t'][h%4] float4 quads
__device__ float g_P[(size_t)B * H * T];

#define K2LOG2E 2.885390082f  // 2*log2(e)

__device__ __forceinline__ float ex2f(float x) {
    float r;
    asm("ex2.approx.f32 %0, %1;" : "=f"(r) : "f"(x));
    return r;
}
__device__ __forceinline__ float rcpf(float x) {
    float r;
    asm("rcp.approx.f32 %0, %1;" : "=f"(r) : "f"(x));
    return r;
}
__device__ __forceinline__ float copysign_bits(float mag, float sgn) {
    unsigned int m = __float_as_uint(mag) & 0x7fffffffu;
    unsigned int s = __float_as_uint(sgn) & 0x80000000u;
    return __uint_as_float(m | s);
}

// ---- gate tanh: negative-exponent safe form + Newton (accurate, NaN-proof) ----
__device__ __forceinline__ float tanh_safe(float x) {
    float y = x * K2LOG2E;
    float m = fminf(y, -y);         // -|y|
    float E = ex2f(m);              // e^{-2|x|} in (0,1]
    float den = E + 1.0f;
    float r = rcpf(den);
    r = r * fmaf(-den, r, 2.0f);    // Newton (den in [1,2], safe)
    float t = (1.0f - E) * r;
    return copysign_bits(t, x);
}

// ---------------- P = 2^{clamp(2log2e * (enc @ W1), <=15)}, transposed+interleaved ----------------
__global__ void __launch_bounds__(256) w1e_kernel(const float* __restrict__ enc,
                                                  const float* __restrict__ W1) {
    extern __shared__ float smem[];
    float* sW1 = smem;               // 128*128
    float* senc = smem + 128 * 128;  // 64 * 129 padded
    int tid = threadIdx.x;
    int b = blockIdx.x >> 3;
    int t0 = (blockIdx.x & 7) * 64;

    for (int i = tid; i < 128 * 128; i += 256) sW1[i] = W1[i];
    for (int i = tid; i < 64 * 128; i += 256) {
        int r = i >> 7, k = i & 127;
        senc[r * 129 + k] = enc[((size_t)b * T + t0 + r) * H + k];
    }
    __syncthreads();

    int t = tid & 63, hg = tid >> 6;
    float acc[32];
#pragma unroll
    for (int i = 0; i < 32; i++) acc[i] = 0.0f;
#pragma unroll 4
    for (int k = 0; k < 128; k++) {
        float e = senc[t * 129 + k];
        const float4* w4 = (const float4*)(sW1 + k * 128 + hg * 32);
#pragma unroll
        for (int q = 0; q < 8; q++) {
            float4 w = w4[q];
            acc[q * 4 + 0] = fmaf(e, w.x, acc[q * 4 + 0]);
            acc[q * 4 + 1] = fmaf(e, w.y, acc[q * 4 + 1]);
            acc[q * 4 + 2] = fmaf(e, w.z, acc[q * 4 + 2]);
            acc[q * 4 + 3] = fmaf(e, w.w, acc[q * 4 + 3]);
        }
    }
    float4* gp = (float4*)g_P;
#pragma unroll
    for (int i4 = 0; i4 < 8; i4++) {
        float4 o = make_float4(ex2f(fminf(acc[i4 * 4] * K2LOG2E, 15.0f)),
                               ex2f(fminf(acc[i4 * 4 + 1] * K2LOG2E, 15.0f)),
                               ex2f(fminf(acc[i4 * 4 + 2] * K2LOG2E, 15.0f)),
                               ex2f(fminf(acc[i4 * 4 + 3] * K2LOG2E, 15.0f)));
        gp[((size_t)b * 32 + hg * 8 + i4) * T + t0 + t] = o;
    }
}

// ---------------- persistent per-batch decoder: 512 threads, 1 t' per thread ----------------
__global__ void __launch_bounds__(512, 2) decoder_kernel(
    const float* __restrict__ x, const float* __restrict__ h0,
    const float* __restrict__ c0, const float* __restrict__ kern,
    const float* __restrict__ reck, const float* __restrict__ bias,
    const float* __restrict__ W2, const float* __restrict__ V,
    float* __restrict__ out) {
    __shared__ float sh[H];
    __shared__ float4 sEu4[32];     // Eu = 2^{u'} quads
    __shared__ float4 sv4[32];      // -2V quads
    __shared__ float sVs[H];
    __shared__ float4 spart4[512];  // phase A/C partials (8 KB, reused)
    __shared__ float sact[G4];      // gate activations
    __shared__ float sK0[G4], sK1[G4], sb[G4];
    __shared__ float sx[T * 2];
    __shared__ float sptr[2];
    __shared__ float s_sumV;
    __shared__ float rv[16];
    __shared__ int ri[16];

    int tid = threadIdx.x;
    int b = blockIdx.x;
    int lane = tid & 31, wid = tid >> 5;

    for (int i = tid; i < T * 2; i += 512) sx[i] = x[(size_t)b * T * 2 + i];
    sK0[tid] = kern[tid];
    sK1[tid] = kern[G4 + tid];
    sb[tid] = bias[tid];
    if (tid < H) { sh[tid] = h0[b * H + tid]; sVs[tid] = V[tid]; }
    float creg = (tid < H) ? c0[b * H + tid] : 0.0f;
    if (tid == 0) { sptr[0] = 1.0f; sptr[1] = 1.0f; }
    __syncthreads();
    if (tid < H) ((float*)sv4)[tid] = -2.0f * sVs[tid];
    if (tid == 0) {
        float sv = 0.0f;
        for (int h = 0; h < H; h++) sv += sVs[h];
        s_sumV = sv;
    }
    __syncthreads();
    float sumV = s_sumV;

    const float4* wp4 = (const float4*)g_P + (size_t)b * 32 * T + tid;
    bool is_g = ((tid >> 7) == 2);  // warp-uniform: g-gate quarter

    for (int s = 0; s < T; s++) {
        // ---- A: partial z, thread (p = h-quarter, q = gate quad): 32 x LDG.128 ----
        {
            int p = tid >> 7, q = tid & 127;
            const float* rp = reck + tid;
            float z = 0.0f;
            (void)p; (void)q;
#pragma unroll 8
            for (int h = 0; h < H; h++)
                z = fmaf(sh[h], __ldg(rp + (size_t)h * G4), z);
            ((float*)spart4)[tid] = z;
        }
        __syncthreads();

        // ---- B1: z-reduce + activation, one gate per thread (512-way) ----
        {
            const float* sp = (const float*)spart4;
            float p0 = sptr[0], p1 = sptr[1];
            float z = fmaf(p1, sK1[tid], fmaf(p0, sK0[tid], sb[tid])) + sp[tid];
            float t = tanh_safe(is_g ? z : 0.5f * z);
            sact[tid] = is_g ? t : fmaf(0.5f, t, 0.5f);
        }
        __syncthreads();

        // ---- B2: cell update (threads 0..127) ----
        if (tid < H) {
            float c2 = sact[tid + H] * creg + sact[tid] * sact[tid + 2 * H];
            creg = c2;
            sh[tid] = sact[tid + 3 * H] * tanh_safe(c2);
        }
        __syncthreads();

        // ---- C: partial u, thread (p2 = h-16th, g = out quad): scalar loads ----
        {
            int p2 = tid >> 7, j = tid & 127;
            float u = 0.0f;
            const float* w2p = W2 + (size_t)(p2 * 32) * H + j;
#pragma unroll 8
            for (int h = 0; h < 32; h++) {
                u = fmaf(sh[p2 * 32 + h], __ldg(w2p), u);
                w2p += H;
            }
            ((float*)spart4)[tid] = u;
        }
        __syncthreads();

        // ---- C-reduce: Eu[j] = 2^{clamp(u*2log2e)} (threads 0..127) ----
        if (tid < H) {
            const float* sp = (const float*)spart4;
            float u = sp[tid] + sp[tid + 128] + sp[tid + 256] + sp[tid + 384];
            ((float*)sEu4)[tid] = ex2f(fminf(u * K2LOG2E, 15.0f));
        }
        __syncthreads();

        // ---- D: score = sumV + sum quads [4-way combined rcp], d = P*Eu + 1 ----
        float acc0 = 0.0f, acc1 = 0.0f;
#pragma unroll 8
        for (int qd = 0; qd < 32; qd++) {
            float4 P = __ldcg(wp4 + (size_t)qd * T);
            float4 Eu = sEu4[qd];
            float4 Vv = sv4[qd];
            float d0 = fmaf(P.x, Eu.x, 1.0f);
            float d1 = fmaf(P.y, Eu.y, 1.0f);
            float d2 = fmaf(P.z, Eu.z, 1.0f);
            float d3 = fmaf(P.w, Eu.w, 1.0f);
            float d01 = d0 * d1, d23 = d2 * d3;
            float n01 = Vv.x * d1;
            n01 = fmaf(Vv.y, d0, n01);
            float n23 = Vv.z * d3;
            n23 = fmaf(Vv.w, d2, n23);
            float num = n01 * d23;
            num = fmaf(n23, d01, num);
            float r = rcpf(d01 * d23);
            if (qd & 1) acc1 = fmaf(num, r, acc1);
            else        acc0 = fmaf(num, r, acc0);
        }
        float score = sumV + (acc0 + acc1);
        __stcs(out + ((size_t)b * T + s) * T + tid, score);

        // ---- argmax (tie -> lowest index) + pointer select ----
        float best = score;
        int bidx = tid;
#pragma unroll
        for (int o = 16; o > 0; o >>= 1) {
            float ov = __shfl_xor_sync(0xffffffffu, best, o);
            int oi = __shfl_xor_sync(0xffffffffu, bidx, o);
            if (ov > best || (ov == best && oi < bidx)) { best = ov; bidx = oi; }
        }
        if (lane == 0) { rv[wid] = best; ri[wid] = bidx; }
        __syncthreads();
        if (wid == 0) {
            float bb = (lane < 16) ? rv[lane] : rv[0];
            int bi = (lane < 16) ? ri[lane] : ri[0];
#pragma unroll
            for (int o = 8; o > 0; o >>= 1) {
                float ov = __shfl_xor_sync(0xffffffffu, bb, o);
                int oi = __shfl_xor_sync(0xffffffffu, bi, o);
                if (ov > bb || (ov == bb && oi < bi)) { bb = ov; bi = oi; }
            }
            if (lane == 0) {
                sptr[0] = sx[bi * 2];
                sptr[1] = sx[bi * 2 + 1];
            }
        }
        __syncthreads();
    }
}

// ---------------- launch: 2 graph nodes ----------------
extern "C" void kernel_launch(void* const* d_in, const int* in_sizes, int n_in,
                              void* d_out, int out_size) {
    const float* x = (const float*)d_in[0];
    const float* enc = (const float*)d_in[1];
    const float* h0 = (const float*)d_in[2];
    const float* c0 = (const float*)d_in[3];
    const float* kern = (const float*)d_in[4];
    const float* reck = (const float*)d_in[5];
    const float* bias = (const float*)d_in[6];
    const float* W1 = (const float*)d_in[7];
    const float* W2 = (const float*)d_in[8];
    const float* V = (const float*)d_in[9];
    float* out = (float*)d_out;

    const int smem_w1e = (128 * 128 + 64 * 129) * 4;  // 98560 B
    cudaFuncSetAttribute(w1e_kernel, cudaFuncAttributeMaxDynamicSharedMemorySize, smem_w1e);
    w1e_kernel<<<B * 8, 256, smem_w1e>>>(enc, W1);
    decoder_kernel<<<B, 512>>>(x, h0, c0, kern, reck, bias, W2, V, out);
}

// round 16
// speedup vs baseline: 2.0846x; 1.1445x over previous
#include <cuda_runtime.h>

#define B 512
#define T 512
#define H 128
#define G4 (4 * H)  // 512

typedef unsigned long long u64;

// g_P stores P = 2^{min(2*log2e*w1e, 15)} as [b][h/4][t'][perm(h%4)] quads,
// perm = {0,2,1,3} (pair-interleaved for f32x2 lanes)
__device__ float g_P[(size_t)B * H * T];

#define K2LOG2E 2.885390082f  // 2*log2(e)
#define ONE2 0x3F8000003F800000ULL

__device__ __forceinline__ float ex2f(float x) {
    float r;
    asm("ex2.approx.f32 %0, %1;" : "=f"(r) : "f"(x));
    return r;
}
__device__ __forceinline__ float rcpf(float x) {
    float r;
    asm("rcp.approx.f32 %0, %1;" : "=f"(r) : "f"(x));
    return r;
}
__device__ __forceinline__ float copysign_bits(float mag, float sgn) {
    unsigned int m = __float_as_uint(mag) & 0x7fffffffu;
    unsigned int s = __float_as_uint(sgn) & 0x80000000u;
    return __uint_as_float(m | s);
}
// ---- packed f32x2 (sm_100a) ----
__device__ __forceinline__ u64 fma2(u64 a, u64 b, u64 c) {
    u64 d;
    asm("fma.rn.f32x2 %0, %1, %2, %3;" : "=l"(d) : "l"(a), "l"(b), "l"(c));
    return d;
}
__device__ __forceinline__ u64 mul2(u64 a, u64 b) {
    u64 d;
    asm("mul.rn.f32x2 %0, %1, %2;" : "=l"(d) : "l"(a), "l"(b));
    return d;
}
__device__ __forceinline__ void unpack2(u64 v, float& lo, float& hi) {
    asm("mov.b64 {%0, %1}, %2;" : "=f"(lo), "=f"(hi) : "l"(v));
}

// ---- gate tanh: negative-exponent safe form + Newton (accurate, NaN-proof) ----
__device__ __forceinline__ float tanh_safe(float x) {
    float y = x * K2LOG2E;
    float m = fminf(y, -y);         // -|y|
    float E = ex2f(m);              // e^{-2|x|} in (0,1]
    float den = E + 1.0f;
    float r = rcpf(den);
    r = r * fmaf(-den, r, 2.0f);    // Newton (den in [1,2], safe)
    float t = (1.0f - E) * r;
    return copysign_bits(t, x);
}

// perm slot for h-index j within its quad: {0,2,1,3}
__device__ __forceinline__ int perm_slot(int j) {
    return (j & ~3) | ((j & 1) << 1) | ((j >> 1) & 1);
}

// ---------------- P = 2^{clamp(...)}: transposed, pair-interleaved quads ----------------
__global__ void __launch_bounds__(256) w1e_kernel(const float* __restrict__ enc,
                                                  const float* __restrict__ W1) {
    extern __shared__ float smem[];
    float* sW1 = smem;               // 128*128
    float* senc = smem + 128 * 128;  // 64 * 129 padded
    int tid = threadIdx.x;
    int b = blockIdx.x >> 3;
    int t0 = (blockIdx.x & 7) * 64;

    for (int i = tid; i < 128 * 128; i += 256) sW1[i] = W1[i];
    for (int i = tid; i < 64 * 128; i += 256) {
        int r = i >> 7, k = i & 127;
        senc[r * 129 + k] = enc[((size_t)b * T + t0 + r) * H + k];
    }
    __syncthreads();

    int t = tid & 63, hg = tid >> 6;
    float acc[32];
#pragma unroll
    for (int i = 0; i < 32; i++) acc[i] = 0.0f;
#pragma unroll 4
    for (int k = 0; k < 128; k++) {
        float e = senc[t * 129 + k];
        const float4* w4 = (const float4*)(sW1 + k * 128 + hg * 32);
#pragma unroll
        for (int q = 0; q < 8; q++) {
            float4 w = w4[q];
            acc[q * 4 + 0] = fmaf(e, w.x, acc[q * 4 + 0]);
            acc[q * 4 + 1] = fmaf(e, w.y, acc[q * 4 + 1]);
            acc[q * 4 + 2] = fmaf(e, w.z, acc[q * 4 + 2]);
            acc[q * 4 + 3] = fmaf(e, w.w, acc[q * 4 + 3]);
        }
    }
    float4* gp = (float4*)g_P;
#pragma unroll
    for (int i4 = 0; i4 < 8; i4++) {
        // pair-interleaved: slots hold h-offsets {0,2,1,3}
        float4 o = make_float4(ex2f(fminf(acc[i4 * 4 + 0] * K2LOG2E, 15.0f)),
                               ex2f(fminf(acc[i4 * 4 + 2] * K2LOG2E, 15.0f)),
                               ex2f(fminf(acc[i4 * 4 + 1] * K2LOG2E, 15.0f)),
                               ex2f(fminf(acc[i4 * 4 + 3] * K2LOG2E, 15.0f)));
        gp[((size_t)b * 32 + hg * 8 + i4) * T + t0 + t] = o;
    }
}

// ---------------- persistent per-batch decoder: 512 threads, 1 t' per thread ----------------
__global__ void __launch_bounds__(512, 2) decoder_kernel(
    const float* __restrict__ x, const float* __restrict__ h0,
    const float* __restrict__ c0, const float* __restrict__ kern,
    const float* __restrict__ reck, const float* __restrict__ bias,
    const float* __restrict__ W2, const float* __restrict__ V,
    float* __restrict__ out) {
    __shared__ float sh[H];
    __shared__ float4 sEu4[32];     // Eu quads (pair-interleaved)
    __shared__ float4 sv4[32];      // -2V quads (pair-interleaved)
    __shared__ float sVs[H];
    __shared__ float4 spart4[512];  // phase A/C partials (8 KB, reused)
    __shared__ float sact[G4];      // gate activations
    __shared__ float sK0[G4], sK1[G4], sb[G4];
    __shared__ float sx[T * 2];
    __shared__ float sptr[2];
    __shared__ float s_sumV;
    __shared__ float rv[16];
    __shared__ int ri[16];

    int tid = threadIdx.x;
    int b = blockIdx.x;
    int lane = tid & 31, wid = tid >> 5;

    for (int i = tid; i < T * 2; i += 512) sx[i] = x[(size_t)b * T * 2 + i];
    sK0[tid] = kern[tid];
    sK1[tid] = kern[G4 + tid];
    sb[tid] = bias[tid];
    if (tid < H) { sh[tid] = h0[b * H + tid]; sVs[tid] = V[tid]; }
    float creg = (tid < H) ? c0[b * H + tid] : 0.0f;
    if (tid == 0) { sptr[0] = 1.0f; sptr[1] = 1.0f; }
    __syncthreads();
    if (tid < H) ((float*)sv4)[perm_slot(tid)] = -2.0f * sVs[tid];
    if (tid == 0) {
        float sv = 0.0f;
        for (int h = 0; h < H; h++) sv += sVs[h];
        s_sumV = sv;
    }
    __syncthreads();
    float sumV = s_sumV;

    const ulonglong2* wp8 = (const ulonglong2*)((const float4*)g_P + (size_t)b * 32 * T + tid);
    bool is_g = ((tid >> 7) == 2);  // warp-uniform: g-gate quarter

    for (int s = 0; s < T; s++) {
        // ---- A: partial z, thread (p = h-quarter, q = gate quad): 32 x LDG.128 ----
        {
            int p = tid >> 7, q = tid & 127;
            const float4* rk = (const float4*)reck + q;
            float4 a = make_float4(0.f, 0.f, 0.f, 0.f);
            int hb = p * 32;
#pragma unroll 8
            for (int h = 0; h < 32; h++) {
                float hv = sh[hb + h];
                float4 r4 = __ldg(rk + (size_t)(hb + h) * 128);
                a.x = fmaf(hv, r4.x, a.x);
                a.y = fmaf(hv, r4.y, a.y);
                a.z = fmaf(hv, r4.z, a.z);
                a.w = fmaf(hv, r4.w, a.w);
            }
            spart4[tid] = a;  // layout: [p][q]
        }
        __syncthreads();

        // ---- B1: z-reduce + activation, one gate per thread (512-way) ----
        {
            const float* sp = (const float*)spart4;
            float p0 = sptr[0], p1 = sptr[1];
            float z = fmaf(p1, sK1[tid], fmaf(p0, sK0[tid], sb[tid]))
                    + ((sp[tid] + sp[512 + tid]) + (sp[1024 + tid] + sp[1536 + tid]));
            float t = tanh_safe(is_g ? z : 0.5f * z);
            sact[tid] = is_g ? t : fmaf(0.5f, t, 0.5f);
        }
        __syncthreads();

        // ---- B2: cell update (threads 0..127) ----
        if (tid < H) {
            float c2 = sact[tid + H] * creg + sact[tid] * sact[tid + 2 * H];
            creg = c2;
            sh[tid] = sact[tid + 3 * H] * tanh_safe(c2);
        }
        __syncthreads();

        // ---- C: partial u, thread (p2 = h-16th, g = out quad): 8 x LDG.128 ----
        {
            int p2 = tid >> 5, g = tid & 31;
            const float4* w2 = (const float4*)W2 + g;
            float4 a = make_float4(0.f, 0.f, 0.f, 0.f);
            int hb = p2 * 8;
#pragma unroll
            for (int h = 0; h < 8; h++) {
                float hv = sh[hb + h];
                float4 w = __ldg(w2 + (size_t)(hb + h) * 32);
                a.x = fmaf(hv, w.x, a.x);
                a.y = fmaf(hv, w.y, a.y);
                a.z = fmaf(hv, w.z, a.z);
                a.w = fmaf(hv, w.w, a.w);
            }
            spart4[tid] = a;  // layout: [p2][g]
        }
        __syncthreads();

        // ---- C-reduce: Eu[j] = 2^{clamp(u*2log2e)} -> pair-interleaved slot ----
        if (tid < H) {
            const float* sp = (const float*)spart4;
            float u = 0.0f;
#pragma unroll
            for (int p2 = 0; p2 < 16; p2++) u += sp[p2 * 128 + tid];
            ((float*)sEu4)[perm_slot(tid)] = ex2f(fminf(u * K2LOG2E, 15.0f));
        }
        __syncthreads();

        // ---- D: score(t'=tid), f32x2 4-way combined rcp, unroll 8 (no spill) ----
        float acc0 = 0.0f, acc1 = 0.0f;
#pragma unroll 8
        for (int qd = 0; qd < 32; qd++) {
            ulonglong2 Pq = __ldcg(wp8 + (size_t)qd * T);          // {P02, P13}
            ulonglong2 Eq = *(const ulonglong2*)&sEu4[qd];          // {Eu02, Eu13}
            ulonglong2 Vq = *(const ulonglong2*)&sv4[qd];           // {V02, V13}
            u64 dA = fma2(Pq.x, Eq.x, ONE2);   // {d0, d2}
            u64 dB = fma2(Pq.y, Eq.y, ONE2);   // {d1, d3}
            u64 prod = mul2(dA, dB);           // {d0*d1, d2*d3}
            u64 nA = mul2(Vq.x, dB);           // {V0*d1, V2*d3}
            u64 n2 = fma2(Vq.y, dA, nA);       // {n01, n23}
            float px, py, n01, n23;
            unpack2(prod, px, py);
            unpack2(n2, n01, n23);
            float num = fmaf(n23, px, n01 * py);
            float r = rcpf(px * py);
            if (qd & 1) acc1 = fmaf(num, r, acc1);
            else        acc0 = fmaf(num, r, acc0);
        }
        float score = sumV + (acc0 + acc1);
        __stcs(out + ((size_t)b * T + s) * T + tid, score);

        // ---- argmax (tie -> lowest index) + pointer select ----
        float best = score;
        int bidx = tid;
#pragma unroll
        for (int o = 16; o > 0; o >>= 1) {
            float ov = __shfl_xor_sync(0xffffffffu, best, o);
            int oi = __shfl_xor_sync(0xffffffffu, bidx, o);
            if (ov > best || (ov == best && oi < bidx)) { best = ov; bidx = oi; }
        }
        if (lane == 0) { rv[wid] = best; ri[wid] = bidx; }
        __syncthreads();
        if (wid == 0) {
            float bb = (lane < 16) ? rv[lane] : rv[0];
            int bi = (lane < 16) ? ri[lane] : ri[0];
#pragma unroll
            for (int o = 8; o > 0; o >>= 1) {
                float ov = __shfl_xor_sync(0xffffffffu, bb, o);
                int oi = __shfl_xor_sync(0xffffffffu, bi, o);
                if (ov > bb || (ov == bb && oi < bi)) { bb = ov; bi = oi; }
            }
            if (lane == 0) {
                sptr[0] = sx[bi * 2];
                sptr[1] = sx[bi * 2 + 1];
            }
        }
        __syncthreads();
    }
}

// ---------------- launch: 2 graph nodes ----------------
extern "C" void kernel_launch(void* const* d_in, const int* in_sizes, int n_in,
                              void* d_out, int out_size) {
    const float* x = (const float*)d_in[0];
    const float* enc = (const float*)d_in[1];
    const float* h0 = (const float*)d_in[2];
    const float* c0 = (const float*)d_in[3];
    const float* kern = (const float*)d_in[4];
    const float* reck = (const float*)d_in[5];
    const float* bias = (const float*)d_in[6];
    const float* W1 = (const float*)d_in[7];
    const float* W2 = (const float*)d_in[8];
    const float* V = (const float*)d_in[9];
    float* out = (float*)d_out;

    const int smem_w1e = (128 * 128 + 64 * 129) * 4;  // 98560 B
    cudaFuncSetAttribute(w1e_kernel, cudaFuncAttributeMaxDynamicSharedMemorySize, smem_w1e);
    w1e_kernel<<<B * 8, 256, smem_w1e>>>(enc, W1);
    decoder_kernel<<<B, 512>>>(x, h0, c0, kern, reck, bias, W2, V, out);
}